// round 17
// baseline (speedup 1.0000x reference)
#include <cuda_runtime.h>
#include <cuda_bf16.h>

#define BB 16
#define NN 256
#define DD 512
#define PE_ROWS 64   // pos = t - start < x[b,seg] <= 63 -> pos in [0,62]

// 256-bit global stores (sm_100+): one instruction commits 1 KB/warp.
__device__ __forceinline__ void stg256(float* p, float4 a, float4 b) {
    asm volatile("st.global.v8.f32 [%0], {%1,%2,%3,%4,%5,%6,%7,%8};"
                 :: "l"(p), "f"(a.x), "f"(a.y), "f"(a.z), "f"(a.w),
                    "f"(b.x), "f"(b.y), "f"(b.z), "f"(b.w)
                 : "memory");
}

// Variant: 2-row ILP x STG.256 x plain write-back (the one untested cell —
// R6's ILP test was confounded with .cs stores, which cost ~1 µs on their own).
// Per iteration: resolve 2 rows, 8 independent LDS.128, 4 independent STG.256
// (4 KB of writes in flight per warp per serial window).
__global__ __launch_bounds__(1024, 1)
void pe_gather_kernel(const int* __restrict__ x,
                      const float* __restrict__ pos_enc,
                      float* __restrict__ out, int T, int chunk) {
    extern __shared__ float smem[];
    float* s_pe   = smem;                               // PE_ROWS*DD floats (128 KB)
    int*   s_cum  = (int*)(smem + PE_ROWS * DD);        // BB*NN ints (16 KB)
    float* s_zero = (float*)(s_cum + BB * NN);          // DD floats (2 KB)

    const int warp = threadIdx.x >> 5;
    const int lane = threadIdx.x & 31;

    // ---- stage hot pos_enc rows ----
    {
        const float4* src = (const float4*)pos_enc;
        float4* dst = (float4*)s_pe;
        for (int i = threadIdx.x; i < PE_ROWS * DD / 4; i += blockDim.x)
            dst[i] = src[i];
    }
    if (threadIdx.x < DD / 4)
        ((float4*)s_zero)[threadIdx.x] = make_float4(0.f, 0.f, 0.f, 0.f);

    // ---- per-CTA cumsum of x: warps 0..15 each scan one batch row ----
    if (warp < BB) {
        int carry = 0;
        for (int c = 0; c < NN / 32; c++) {
            int idx = c * 32 + lane;
            int v = x[warp * NN + idx];
            #pragma unroll
            for (int off = 1; off < 32; off <<= 1) {
                int n = __shfl_up_sync(0xffffffffu, v, off);
                if (lane >= off) v += n;
            }
            v += carry;
            s_cum[warp * NN + idx] = v;
            carry = __shfl_sync(0xffffffffu, v, 31);
        }
    }
    __syncthreads();

    // ---- contiguous row range for this warp ----
    const long total = (long)BB * T;
    const int warp_global = blockIdx.x * (blockDim.x >> 5) + warp;
    long r0 = (long)warp_global * chunk;
    if (r0 >= total) return;
    long r1 = r0 + chunk; if (r1 > total) r1 = total;

    int b = (int)(r0 / T);            // only division in the kernel
    int t = (int)(r0 - (long)b * T);
    const int* cum = s_cum + b * NN;
    int last = cum[NN - 1];

    // searchsorted(cum, t, 'right'): first seg with cum[seg] > t (257 answers -> 9 steps)
    int seg;
    {
        int lo = 0, hi = NN;
        #pragma unroll
        for (int it = 0; it < 9; it++) {
            if (lo < hi) {
                int mid = (lo + hi) >> 1;
                if (cum[mid] <= t) lo = mid + 1; else hi = mid;
            }
        }
        seg = lo;
    }

    long r = r0;
    while (r < r1) {
        const bool haveB = (r + 1 < r1) && (b < BB);

        // ---- resolve source row A ----
        const float* srcA = s_zero;
        if (t < last) {
            while (cum[seg] <= t) seg++;                 // monotone advance
            const int start = (seg > 0) ? cum[seg - 1] : 0;
            srcA = s_pe + (t - start) * DD;
        }
        bool okB = haveB;
        if (++t == T) {                                  // advance to row B's state
            t = 0; b++;
            if (b < BB) { cum += NN; last = cum[NN - 1]; seg = 0; }
            else okB = false;                            // no table for row B
        }

        // ---- resolve source row B ----
        const float* srcB = s_zero;
        if (okB) {
            if (t < last) {
                while (cum[seg] <= t) seg++;
                const int start = (seg > 0) ? cum[seg - 1] : 0;
                srcB = s_pe + (t - start) * DD;
            }
            if (++t == T) {
                t = 0; b++;
                if (b < BB) { cum += NN; last = cum[NN - 1]; seg = 0; }
            }
        }

        // ---- 8 independent shared loads (lane owns 8l..8l+7 and 256+8l..) ----
        const float4* sa = (const float4*)srcA + lane * 2;
        float4 a0 = sa[0], a1 = sa[1], a2 = sa[64], a3 = sa[65];
        float4 b0, b1, b2, b3;
        if (haveB) {
            const float4* sb = (const float4*)srcB + lane * 2;
            b0 = sb[0]; b1 = sb[1]; b2 = sb[64]; b3 = sb[65];
        }

        // ---- 4 independent 256-bit stores ----
        float* dstA = out + r * (long)DD + lane * 8;
        stg256(dstA,       a0, a1);
        stg256(dstA + 256, a2, a3);
        if (haveB) {
            float* dstB = dstA + DD;
            stg256(dstB,       b0, b1);
            stg256(dstB + 256, b2, b3);
        }

        r += haveB ? 2 : 1;
        if (b >= BB) break;
    }
}

extern "C" void kernel_launch(void* const* d_in, const int* in_sizes, int n_in,
                              void* d_out, int out_size) {
    const int*   x       = (const int*)d_in[0];
    const float* pos_enc = (const float*)d_in[1];
    float*       out     = (float*)d_out;

    const int T = out_size / (BB * DD);

    int sms = 148;
    cudaDeviceGetAttribute(&sms, cudaDevAttrMultiProcessorCount, 0);

    const long total = (long)BB * T;
    const int nwarps = sms * 32;
    const int chunk = (int)((total + nwarps - 1) / nwarps);

    const size_t smem_bytes = (size_t)(PE_ROWS * DD) * sizeof(float)
                            + (size_t)(BB * NN) * sizeof(int)
                            + (size_t)DD * sizeof(float);   // 149504 B
    cudaFuncSetAttribute(pe_gather_kernel,
                         cudaFuncAttributeMaxDynamicSharedMemorySize,
                         (int)smem_bytes);
    pe_gather_kernel<<<sms, 1024, smem_bytes>>>(x, pos_enc, out, T, chunk);
}